// round 3
// baseline (speedup 1.0000x reference)
#include <cuda_runtime.h>
#include <cuda_bf16.h>
#include <cstdint>

// COO SpMM via on-the-fly CSR build (4 kernels), then row-gather SpMM.
// out[i,:] = sum_{e: rows[e]==i} vals[e] * embeds[cols[e],:]

#define N_NODES 100000
#define N_EDGES 1600000
#define D_FEAT  48
#define D_VEC4  12

#define SCAN_N   (N_NODES + 1)          // 100001
#define SCAN_BLK 1024
#define SCAN_NB  ((SCAN_N + SCAN_BLK - 1) / SCAN_BLK)   // 98

// Scratch (static device globals — zero-initialized at module load).
// Invariant maintained: g_counts is all-zero at kernel_launch entry
// (scan kernel re-zeroes it after consuming), g_desc is zeroed by hist.
__device__ int  g_counts[SCAN_N];
__device__ int  g_offs[SCAN_N];
__device__ int  g_cursor[N_NODES];
__device__ unsigned long long g_desc[SCAN_NB];   // lookback: flag<<62 | sum
__device__ int2 g_edges[N_EDGES];                // {col, val_as_int}

// ---------- pass 1: histogram of rows (int4 vectorized) + zero lookback state ----------
__global__ void hist_kernel(const int4* __restrict__ rows4, int n4) {
    if (blockIdx.x == 0 && threadIdx.x < SCAN_NB)
        g_desc[threadIdx.x] = 0ULL;
    int i = blockIdx.x * blockDim.x + threadIdx.x;
    if (i < n4) {
        int4 r = __ldg(&rows4[i]);
        atomicAdd(&g_counts[r.x], 1);
        atomicAdd(&g_counts[r.y], 1);
        atomicAdd(&g_counts[r.z], 1);
        atomicAdd(&g_counts[r.w], 1);
    }
}

// ---------- pass 2: single-launch exclusive scan (decoupled lookback) ----------
// 98 blocks, all co-resident on 148 SMs => lookback is deadlock-free.
__global__ void __launch_bounds__(SCAN_BLK)
scan_lookback_kernel() {
    __shared__ int warp_sums[32];
    __shared__ int s_exclusive;

    int bid = blockIdx.x;
    int i = bid * SCAN_BLK + threadIdx.x;
    int v = (i < SCAN_N) ? g_counts[i] : 0;
    if (i < SCAN_N) g_counts[i] = 0;      // restore zero invariant for next call

    int lane = threadIdx.x & 31, wid = threadIdx.x >> 5;

    // block-wide inclusive scan
    int inc = v;
#pragma unroll
    for (int d = 1; d < 32; d <<= 1) {
        int t = __shfl_up_sync(0xffffffffu, inc, d);
        if (lane >= d) inc += t;
    }
    if (lane == 31) warp_sums[wid] = inc;
    __syncthreads();
    if (wid == 0) {
        int s = warp_sums[lane];
#pragma unroll
        for (int d = 1; d < 32; d <<= 1) {
            int t = __shfl_up_sync(0xffffffffu, s, d);
            if (lane >= d) s += t;
        }
        warp_sums[lane] = s;
    }
    __syncthreads();
    int base = (wid > 0) ? warp_sums[wid - 1] : 0;
    int local_excl = base + inc - v;
    int block_sum = warp_sums[31];

    // publish partial (block 0: inclusive directly)
    if (threadIdx.x == 0) {
        unsigned long long flag = (bid == 0) ? 2ULL : 1ULL;
        *(volatile unsigned long long*)&g_desc[bid] =
            (flag << 62) | (unsigned long long)(unsigned)block_sum;
        __threadfence();
        if (bid == 0) s_exclusive = 0;
    }

    // warp 0 does the lookback
    if (bid > 0 && wid == 0) {
        int exclusive = 0;
        int j = bid - 1;
        while (true) {
            int idx = j - lane;
            int flag, val;
            if (idx >= 0) {
                unsigned long long d;
                do {
                    d = *(volatile unsigned long long*)&g_desc[idx];
                    flag = (int)(d >> 62);
                } while (flag == 0);
                val = (int)(d & 0xffffffffULL);
            } else { flag = 2; val = 0; }
            unsigned mask = __ballot_sync(0xffffffffu, flag == 2);
            int contrib;
            if (mask) {
                int steps = __ffs(mask) - 1;   // nearest inclusive predecessor
                contrib = (lane <= steps) ? val : 0;
            } else {
                contrib = val;                 // all partial: take them, keep walking
            }
#pragma unroll
            for (int d = 16; d; d >>= 1)
                contrib += __shfl_down_sync(0xffffffffu, contrib, d);
            contrib = __shfl_sync(0xffffffffu, contrib, 0);
            exclusive += contrib;
            if (mask) break;
            j -= 32;
        }
        if (lane == 0) {
            __threadfence();
            *(volatile unsigned long long*)&g_desc[bid] =
                (2ULL << 62) | (unsigned long long)(unsigned)(exclusive + block_sum);
            s_exclusive = exclusive;
        }
    }
    __syncthreads();

    int off = s_exclusive + local_excl;
    if (i < SCAN_N) {
        g_offs[i] = off;
        if (i < N_NODES) g_cursor[i] = off;
    }
}

// ---------- pass 3: scatter edges into CSR bins ----------
__global__ void scatter_kernel(const int* __restrict__ rows,
                               const int* __restrict__ cols,
                               const float* __restrict__ vals, int n) {
    int e = blockIdx.x * blockDim.x + threadIdx.x;
    if (e < n) {
        int r = rows[e];
        int p = atomicAdd(&g_cursor[r], 1);
        g_edges[p] = make_int2(cols[e], __float_as_int(vals[e]));
    }
}

// ---------- pass 4: row-gather SpMM ----------
// 16-lane groups per row; 12 active lanes each load one float4 of the
// gathered embedding row (LDG.128, ~2 L1 wavefronts/edge). All 16 lanes
// share the loop bounds -> no divergence inside the group.
__global__ void __launch_bounds__(256)
spmm_csr_kernel(const float4* __restrict__ embeds4,  // [N,12] float4
                float4* __restrict__ out4) {         // [N,12] float4
    int row  = blockIdx.x * 16 + (threadIdx.x >> 4);
    int lane = threadIdx.x & 15;
    if (row >= N_NODES) return;

    int s = g_offs[row];
    int t = g_offs[row + 1];

    float ax = 0.f, ay = 0.f, az = 0.f, aw = 0.f;
    int e = s;
    for (; e + 2 <= t; e += 2) {
        int2 p0 = __ldg(&g_edges[e]);
        int2 p1 = __ldg(&g_edges[e + 1]);
        if (lane < 12) {
            float4 x0 = __ldg(&embeds4[(size_t)p0.x * D_VEC4 + lane]);
            float4 x1 = __ldg(&embeds4[(size_t)p1.x * D_VEC4 + lane]);
            float v0 = __int_as_float(p0.y);
            float v1 = __int_as_float(p1.y);
            ax += v0 * x0.x + v1 * x1.x;
            ay += v0 * x0.y + v1 * x1.y;
            az += v0 * x0.z + v1 * x1.z;
            aw += v0 * x0.w + v1 * x1.w;
        }
    }
    if (e < t) {
        int2 p = __ldg(&g_edges[e]);
        if (lane < 12) {
            float4 x = __ldg(&embeds4[(size_t)p.x * D_VEC4 + lane]);
            float v = __int_as_float(p.y);
            ax += v * x.x; ay += v * x.y; az += v * x.z; aw += v * x.w;
        }
    }

    if (lane < 12)
        out4[(size_t)row * D_VEC4 + lane] = make_float4(ax, ay, az, aw);
}

extern "C" void kernel_launch(void* const* d_in, const int* in_sizes, int n_in,
                              void* d_out, int out_size) {
    const int*   rows   = (const int*)d_in[0];
    const int*   cols   = (const int*)d_in[1];
    const float* vals   = (const float*)d_in[2];
    const float4* embeds4 = (const float4*)d_in[3];
    float4* out4 = (float4*)d_out;

    int n_edges = in_sizes[0];
    int n4 = n_edges / 4;   // 1.6M divisible by 4

    hist_kernel<<<(n4 + 255) / 256, 256>>>((const int4*)rows, n4);
    scan_lookback_kernel<<<SCAN_NB, SCAN_BLK>>>();
    scatter_kernel<<<(n_edges + 255) / 256, 256>>>(rows, cols, vals, n_edges);
    spmm_csr_kernel<<<(N_NODES + 15) / 16, 256>>>(embeds4, out4);
}